// round 16
// baseline (speedup 1.0000x reference)
#include <cuda_runtime.h>
#include <math.h>
#include <stdint.h>

#define BB 4
#define NN 40960
#define KK 16
#define HH 16
#define DD 32
#define BN_EPS 1e-5f
#define RS 20            // padded row stride (floats) for mma-fed tiles
#define RSB 80           // row stride bytes
#define PTB (KK * RSB)   // bytes per point tile (1280)
#define LOG2E 1.4426950408889634f

__device__ float g_feat_t[BB * NN * HH];
__device__ float g_agg1[BB * NN * HH];
__device__ float g_fx1[(size_t)BB * NN * KK * HH];  // f_xyz1 [b,n,k,16]

__device__ __forceinline__ float lrelu(float y) { return fmaxf(y, 0.2f * y); }

__device__ __forceinline__ uint32_t LDSU(unsigned addr) {
    uint32_t v; asm volatile("ld.shared.b32 %0, [%1];" : "=r"(v) : "r"(addr)); return v;
}
__device__ __forceinline__ float LDSF(unsigned addr) {
    float v; asm volatile("ld.shared.f32 %0, [%1];" : "=f"(v) : "r"(addr)); return v;
}
__device__ __forceinline__ uint32_t CVT_TF32(float x) {
    uint32_t r; asm("cvt.rna.tf32.f32 %0, %1;" : "=r"(r) : "f"(x)); return r;
}
__device__ __forceinline__ float EX2(float x) {
    float r; asm("ex2.approx.f32 %0, %1;" : "=f"(r) : "f"(x)); return r;
}

// tf32 mma m16n8k8: D += A*B
#define MMA_TF32(d, a, b0, b1) \
    asm volatile("mma.sync.aligned.m16n8k8.row.col.f32.tf32.tf32.f32 " \
        "{%0,%1,%2,%3}, {%4,%5,%6,%7}, {%8,%9}, {%0,%1,%2,%3};" \
        : "+f"((d)[0]), "+f"((d)[1]), "+f"((d)[2]), "+f"((d)[3]) \
        : "r"((a)[0]), "r"((a)[1]), "r"((a)[2]), "r"((a)[3]), "r"(b0), "r"(b1))

// ---- cp.async helpers ----
__device__ __forceinline__ void cp16(unsigned dst, const float* src) {
    asm volatile("cp.async.cg.shared.global [%0], [%1], 16;" :: "r"(dst), "l"(src));
}
__device__ __forceinline__ void cp4(unsigned dst, const float* src) {
    asm volatile("cp.async.ca.shared.global [%0], [%1], 4;" :: "r"(dst), "l"(src));
}
__device__ __forceinline__ void cp_commit() {
    asm volatile("cp.async.commit_group;");
}
template <int N> __device__ __forceinline__ void cp_wait() {
    asm volatile("cp.async.wait_group %0;" :: "n"(N));
}

// fc scores: 32 channels x 16 j for one point -> s[16] (lane-distributed)
__device__ __forceinline__ void fc_scores(const uint32_t* aw, unsigned fbuf,
                                          unsigned cbuf, int g, int tq, float* s) {
    #pragma unroll
    for (int nT = 0; nT < 2; nT++) {
        float c0[4] = {0.f, 0.f, 0.f, 0.f}, c1[4] = {0.f, 0.f, 0.f, 0.f};
        int j = g + 8 * nT;
        unsigned xf = fbuf + j * RSB;
        unsigned xc = cbuf + j * RSB;
        #pragma unroll
        for (int kT = 0; kT < 4; kT++) {
            unsigned base = (kT < 2) ? (xf + (8 * kT + tq) * 4)
                                     : (xc + (8 * (kT - 2) + tq) * 4);
            uint32_t b0v = LDSU(base), b1v = LDSU(base + 16);
            MMA_TF32(c0, &aw[(0 * 4 + kT) * 4], b0v, b1v);
            MMA_TF32(c1, &aw[(1 * 4 + kT) * 4], b0v, b1v);
        }
        #pragma unroll
        for (int q = 0; q < 4; q++) {
            s[(nT * 2 + 0) * 4 + q] = c0[q];
            s[(nT * 2 + 1) * 4 + q] = c1[q];
        }
    }
}

// softmax-pool: s holds exp'd scores; result valid on tq==0 lanes
__device__ __forceinline__ void softpool(const float* s, unsigned fbuf, unsigned cbuf,
                                         int g, int tq, float4& r) {
    float p0 = s[0] + s[1] + s[8]  + s[9];
    float p1 = s[2] + s[3] + s[10] + s[11];
    float p2 = s[4] + s[5] + s[12] + s[13];
    float p3 = s[6] + s[7] + s[14] + s[15];
    p0 += __shfl_xor_sync(0xffffffffu, p0, 1); p0 += __shfl_xor_sync(0xffffffffu, p0, 2);
    p1 += __shfl_xor_sync(0xffffffffu, p1, 1); p1 += __shfl_xor_sync(0xffffffffu, p1, 2);
    p2 += __shfl_xor_sync(0xffffffffu, p2, 1); p2 += __shfl_xor_sync(0xffffffffu, p2, 2);
    p3 += __shfl_xor_sync(0xffffffffu, p3, 1); p3 += __shfl_xor_sync(0xffffffffu, p3, 2);
    int j0 = 2 * tq, j1 = j0 + 1, j8 = j0 + 8, j9 = j0 + 9;
    unsigned cF0 = g * 4, cF1 = (g + 8) * 4;
    float a0 = LDSF(fbuf + j0 * RSB + cF0) * s[0] + LDSF(fbuf + j1 * RSB + cF0) * s[1]
             + LDSF(fbuf + j8 * RSB + cF0) * s[8] + LDSF(fbuf + j9 * RSB + cF0) * s[9];
    float a1 = LDSF(fbuf + j0 * RSB + cF1) * s[2] + LDSF(fbuf + j1 * RSB + cF1) * s[3]
             + LDSF(fbuf + j8 * RSB + cF1) * s[10] + LDSF(fbuf + j9 * RSB + cF1) * s[11];
    float a2 = LDSF(cbuf + j0 * RSB + cF0) * s[4] + LDSF(cbuf + j1 * RSB + cF0) * s[5]
             + LDSF(cbuf + j8 * RSB + cF0) * s[12] + LDSF(cbuf + j9 * RSB + cF0) * s[13];
    float a3 = LDSF(cbuf + j0 * RSB + cF1) * s[6] + LDSF(cbuf + j1 * RSB + cF1) * s[7]
             + LDSF(cbuf + j8 * RSB + cF1) * s[14] + LDSF(cbuf + j9 * RSB + cF1) * s[15];
    a0 += __shfl_xor_sync(0xffffffffu, a0, 1); a0 += __shfl_xor_sync(0xffffffffu, a0, 2);
    a1 += __shfl_xor_sync(0xffffffffu, a1, 1); a1 += __shfl_xor_sync(0xffffffffu, a1, 2);
    a2 += __shfl_xor_sync(0xffffffffu, a2, 1); a2 += __shfl_xor_sync(0xffffffffu, a2, 2);
    a3 += __shfl_xor_sync(0xffffffffu, a3, 1); a3 += __shfl_xor_sync(0xffffffffu, a3, 2);
    r.x = __fdividef(a0, p0); r.y = __fdividef(a1, p1);
    r.z = __fdividef(a2, p2); r.w = __fdividef(a3, p3);
}

// ---------------------------------------------------------------------------
__global__ void transpose_feat_kernel(const float* __restrict__ feature) {
    __shared__ float tile[HH][64 + 1];
    int b = blockIdx.y;
    int n0 = blockIdx.x * 64;
    int t = threadIdx.x;
    int i = t & 63, cq = t >> 6;
    #pragma unroll
    for (int cc = cq; cc < HH; cc += 4)
        tile[cc][i] = feature[(b * HH + cc) * NN + n0 + i];
    __syncthreads();
    int c = t & 15, iq = t >> 4;
    #pragma unroll
    for (int ii = iq; ii < 64; ii += 16)
        g_feat_t[(b * NN + n0 + ii) * HH + c] = tile[c][ii];
}

// ---------------------------------------------------------------------------
// Stage 1 smem (dynamic): 8 warps/CTA, 2 points per iteration per warp.
// ---------------------------------------------------------------------------
struct S1Smem {
    float feat[8][4][KK][RS];   // gather ring (4 point-buffers)
    float nxyz[8][4][KK][4];
    float fxyz[8][2][KK][RS];   // pair
    float conv[8][2][KK][RS];   // pair
    float agg[8][8][36];
    int   idx[8][8][KK];
    float cxyz[8][8][3];
};

__global__ void __launch_bounds__(256, 2) stage1_kernel(
    const float* __restrict__ xyz, const int* __restrict__ nidx,
    const float* __restrict__ w1, const float* __restrict__ b1,
    const float* __restrict__ g1, const float* __restrict__ be1,
    const float* __restrict__ fc1w, const float* __restrict__ fc1b,
    const float* __restrict__ ap1w, const float* __restrict__ ap1b,
    const float* __restrict__ ap1g, const float* __restrict__ ap1be)
{
    extern __shared__ __align__(16) char smem_raw[];
    S1Smem* sm = (S1Smem*)smem_raw;

    const int warp = threadIdx.x >> 5;
    const int lane = threadIdx.x & 31;
    const int g = lane >> 2, tq = lane & 3;
    const float inv_bn = rsqrtf(1.0f + BN_EPS);

    // conv1 weight fragments (BN folded, K padded 10->16)
    uint32_t aw1[8]; float bb1c0, bb1c1;
    {
        float s0 = g1[g] * inv_bn, s1 = g1[g + 8] * inv_bn;
        #pragma unroll
        for (int kT = 0; kT < 2; kT++) {
            int d0 = 8 * kT + tq, d1 = d0 + 4;
            float w00 = (d0 < 10) ? w1[g * 10 + d0] * s0 : 0.f;
            float w10 = (d0 < 10) ? w1[(g + 8) * 10 + d0] * s1 : 0.f;
            float w01 = (d1 < 10) ? w1[g * 10 + d1] * s0 : 0.f;
            float w11 = (d1 < 10) ? w1[(g + 8) * 10 + d1] * s1 : 0.f;
            aw1[kT * 4 + 0] = CVT_TF32(w00); aw1[kT * 4 + 1] = CVT_TF32(w10);
            aw1[kT * 4 + 2] = CVT_TF32(w01); aw1[kT * 4 + 3] = CVT_TF32(w11);
        }
        bb1c0 = b1[g] * s0 + be1[g];
        bb1c1 = b1[g + 8] * s1 + be1[g + 8];
    }
    // fc weight fragments (log2e folded)
    uint32_t aw[32];
    #pragma unroll
    for (int mT = 0; mT < 2; mT++)
        #pragma unroll
        for (int kT = 0; kT < 4; kT++) {
            int r0 = 16 * mT + g, r1 = r0 + 8, d0 = 8 * kT + tq, d1 = d0 + 4;
            int o = (mT * 4 + kT) * 4;
            aw[o + 0] = CVT_TF32(fc1w[r0 * DD + d0] * LOG2E);
            aw[o + 1] = CVT_TF32(fc1w[r1 * DD + d0] * LOG2E);
            aw[o + 2] = CVT_TF32(fc1w[r0 * DD + d1] * LOG2E);
            aw[o + 3] = CVT_TF32(fc1w[r1 * DD + d1] * LOG2E);
        }

    const int b  = blockIdx.x / (NN / 64);
    const int n0 = (blockIdx.x % (NN / 64)) * 64;
    const int pbase = b * NN + n0 + warp * 8;

    const unsigned feat_a = (unsigned)__cvta_generic_to_shared(&sm->feat[warp][0][0][0]);
    const unsigned nxyz_a = (unsigned)__cvta_generic_to_shared(&sm->nxyz[warp][0][0][0]);
    const unsigned fxyz_a = (unsigned)__cvta_generic_to_shared(&sm->fxyz[warp][0][0][0]);
    const unsigned conv_a = (unsigned)__cvta_generic_to_shared(&sm->conv[warp][0][0][0]);
    const unsigned agg_a  = (unsigned)__cvta_generic_to_shared(&sm->agg[warp][0][0]);

    {
        int4 iv = *(const int4*)(nidx + (size_t)pbase * KK + lane * 4);
        *(int4*)&sm->idx[warp][lane >> 2][(lane & 3) * 4] = iv;
    }
    if (lane < 24) sm->cxyz[warp][lane / 3][lane % 3] = xyz[pbase * 3 + lane];
    // zero-pad geometry rows d=10..15 for both pair buffers
    {
        int pt = lane >> 4, j = lane & 15;
        ((float2*)&sm->fxyz[warp][pt][j][10])[0] = make_float2(0.f, 0.f);
        ((float4*)&sm->fxyz[warp][pt][j][12])[0] = make_float4(0.f, 0.f, 0.f, 0.f);
    }
    __syncthreads();

    const int j2 = lane >> 1, h2 = lane & 1;

    #pragma unroll
    for (int s = 0; s < 4; s++) {
        int idx = sm->idx[warp][s][j2];
        const float* src = g_feat_t + (size_t)(b * NN + idx) * HH + h2 * 8;
        unsigned d = feat_a + s * PTB + j2 * RSB + h2 * 32;
        cp16(d, src); cp16(d + 16, src + 4);
        if (lane < KK) {
            int ix = sm->idx[warp][s][lane];
            const float* xs = xyz + (size_t)(b * NN + ix) * 3;
            unsigned dn = nxyz_a + s * 256 + lane * 16;
            cp4(dn, xs); cp4(dn + 4, xs + 1); cp4(dn + 8, xs + 2);
        }
        cp_commit();
    }

    #pragma unroll
    for (int t = 0; t < 4; t++) {
        const int p0 = 2 * t, p1 = p0 + 1;
        const int pn0 = pbase + p0, pn1 = pbase + p1;
        const int buf0 = p0 & 3;
        if (t < 3) cp_wait<2>(); else cp_wait<0>();
        __syncwarp();

        // geometry: all 32 lanes (pt = lane>>4)
        {
            int pt = lane >> 4, j = lane & 15;
            const float* np_ = &sm->nxyz[warp][buf0 + pt][j][0];
            float nx = np_[0], ny = np_[1], nz = np_[2];
            const float* cp_ = &sm->cxyz[warp][p0 + pt][0];
            float cx = cp_[0], cy = cp_[1], cz = cp_[2];
            float rx = cx - nx, ry = cy - ny, rz = cz - nz;
            float dis = sqrtf(rx * rx + ry * ry + rz * rz);
            float4* row = (float4*)&sm->fxyz[warp][pt][j][0];
            row[0] = make_float4(dis, rx, ry, rz);
            row[1] = make_float4(cx, cy, cz, nx);
            ((float2*)&sm->fxyz[warp][pt][j][8])[0] = make_float2(ny, nz);
        }
        __syncwarp();

        // conv1 via tf32 mma for both points
        #pragma unroll
        for (int pt = 0; pt < 2; pt++) {
            size_t gb = (size_t)(pt ? pn1 : pn0) * (KK * HH);
            #pragma unroll
            for (int nT = 0; nT < 2; nT++) {
                float c[4] = {bb1c0, bb1c0, bb1c1, bb1c1};
                unsigned xb = fxyz_a + pt * PTB + (8 * nT + g) * RSB;
                #pragma unroll
                for (int kT = 0; kT < 2; kT++) {
                    unsigned base = xb + (8 * kT + tq) * 4;
                    uint32_t b0v = LDSU(base);
                    uint32_t b1v = LDSU(base + 16);
                    MMA_TF32(c, &aw1[kT * 4], b0v, b1v);
                }
                int j0 = 8 * nT + 2 * tq, j1 = j0 + 1;
                float v0 = lrelu(c[0]), v1 = lrelu(c[1]);
                float v2 = lrelu(c[2]), v3 = lrelu(c[3]);
                sm->conv[warp][pt][j0][g] = v0;     sm->conv[warp][pt][j1][g] = v1;
                sm->conv[warp][pt][j0][g + 8] = v2; sm->conv[warp][pt][j1][g + 8] = v3;
                g_fx1[gb + j0 * HH + g] = v0;     g_fx1[gb + j1 * HH + g] = v1;
                g_fx1[gb + j0 * HH + g + 8] = v2; g_fx1[gb + j1 * HH + g + 8] = v3;
            }
        }
        __syncwarp();

        // fc + softmax + pool, both points interleaved
        const unsigned fb0 = feat_a + (buf0 + 0) * PTB, cb0 = conv_a + 0 * PTB;
        const unsigned fb1 = feat_a + (buf0 + 1) * PTB, cb1 = conv_a + 1 * PTB;
        float s0v[16], s1v[16];
        fc_scores(aw, fb0, cb0, g, tq, s0v);
        fc_scores(aw, fb1, cb1, g, tq, s1v);
        #pragma unroll
        for (int i = 0; i < 16; i++) { s0v[i] = EX2(s0v[i]); s1v[i] = EX2(s1v[i]); }
        float4 r0, r1;
        softpool(s0v, fb0, cb0, g, tq, r0);
        softpool(s1v, fb1, cb1, g, tq, r1);
        if (tq == 0) {
            sm->agg[warp][p0][g]      = r0.x; sm->agg[warp][p0][g + 8]  = r0.y;
            sm->agg[warp][p0][g + 16] = r0.z; sm->agg[warp][p0][g + 24] = r0.w;
            sm->agg[warp][p1][g]      = r1.x; sm->agg[warp][p1][g + 8]  = r1.y;
            sm->agg[warp][p1][g + 16] = r1.z; sm->agg[warp][p1][g + 24] = r1.w;
        }

        // prefetch points p0+4, p0+5
        if (t < 2) {
            #pragma unroll
            for (int pt = 0; pt < 2; pt++) {
                int sN = p0 + 4 + pt;
                int idx = sm->idx[warp][sN][j2];
                const float* src = g_feat_t + (size_t)(b * NN + idx) * HH + h2 * 8;
                unsigned d = feat_a + (sN & 3) * PTB + j2 * RSB + h2 * 32;
                cp16(d, src); cp16(d + 16, src + 4);
                if (lane < KK) {
                    int ix = sm->idx[warp][sN][lane];
                    const float* xs = xyz + (size_t)(b * NN + ix) * 3;
                    unsigned dn = nxyz_a + (sN & 3) * 256 + lane * 16;
                    cp4(dn, xs); cp4(dn + 4, xs + 1); cp4(dn + 8, xs + 2);
                }
                cp_commit();
            }
        }
    }
    __syncwarp();   // agg visible for batched mlp

    // batched mlp (32->16) for 8 points via tf32 mma
    {
        float s0 = ap1g[g] * inv_bn, s1 = ap1g[g + 8] * inv_bn;
        float c[4];
        c[0] = c[1] = ap1b[g] * s0 + ap1be[g];
        c[2] = c[3] = ap1b[g + 8] * s1 + ap1be[g + 8];
        #pragma unroll
        for (int kT = 0; kT < 4; kT++) {
            int d0 = 8 * kT + tq, d1 = d0 + 4;
            uint32_t af[4];
            af[0] = CVT_TF32(ap1w[g * DD + d0] * s0);
            af[1] = CVT_TF32(ap1w[(g + 8) * DD + d0] * s1);
            af[2] = CVT_TF32(ap1w[g * DD + d1] * s0);
            af[3] = CVT_TF32(ap1w[(g + 8) * DD + d1] * s1);
            uint32_t b0v = CVT_TF32(LDSF(agg_a + g * 144 + d0 * 4));
            uint32_t b1v = CVT_TF32(LDSF(agg_a + g * 144 + d1 * 4));
            MMA_TF32(c, af, b0v, b1v);
        }
        int p0i = pbase + 2 * tq, p1i = p0i + 1;
        g_agg1[(size_t)p0i * HH + g]     = lrelu(c[0]);
        g_agg1[(size_t)p1i * HH + g]     = lrelu(c[1]);
        g_agg1[(size_t)p0i * HH + g + 8] = lrelu(c[2]);
        g_agg1[(size_t)p1i * HH + g + 8] = lrelu(c[3]);
    }
}

// ---------------------------------------------------------------------------
// Stage 2 smem (dynamic): 8 warps/CTA, 2 points per iteration per warp.
// ---------------------------------------------------------------------------
struct S2Smem {
    float feat[8][4][KK][RS];
    float fx1[8][4][KK][RS];
    float conv[8][2][KK][RS];
    float agg[8][8][36];
    int   idx[8][8][KK];
};

__global__ void __launch_bounds__(256, 2) stage2_kernel(
    const int* __restrict__ nidx,
    const float* __restrict__ w2, const float* __restrict__ b2,
    const float* __restrict__ g2, const float* __restrict__ be2,
    const float* __restrict__ fc2w, const float* __restrict__ fc2b,
    const float* __restrict__ ap2w, const float* __restrict__ ap2b,
    const float* __restrict__ ap2g, const float* __restrict__ ap2be,
    float* __restrict__ out)
{
    extern __shared__ __align__(16) char smem_raw[];
    S2Smem* sm = (S2Smem*)smem_raw;

    const int warp = threadIdx.x >> 5;
    const int lane = threadIdx.x & 31;
    const int g = lane >> 2, tq = lane & 3;
    const float inv_bn = rsqrtf(1.0f + BN_EPS);

    uint32_t aw2[8]; float bb2c0, bb2c1;
    {
        float s0 = g2[g] * inv_bn, s1 = g2[g + 8] * inv_bn;
        #pragma unroll
        for (int kT = 0; kT < 2; kT++) {
            int d0 = 8 * kT + tq, d1 = d0 + 4;
            aw2[kT * 4 + 0] = CVT_TF32(w2[g * HH + d0] * s0);
            aw2[kT * 4 + 1] = CVT_TF32(w2[(g + 8) * HH + d0] * s1);
            aw2[kT * 4 + 2] = CVT_TF32(w2[g * HH + d1] * s0);
            aw2[kT * 4 + 3] = CVT_TF32(w2[(g + 8) * HH + d1] * s1);
        }
        bb2c0 = b2[g] * s0 + be2[g];
        bb2c1 = b2[g + 8] * s1 + be2[g + 8];
    }
    uint32_t aw[32];
    #pragma unroll
    for (int mT = 0; mT < 2; mT++)
        #pragma unroll
        for (int kT = 0; kT < 4; kT++) {
            int r0 = 16 * mT + g, r1 = r0 + 8, d0 = 8 * kT + tq, d1 = d0 + 4;
            int o = (mT * 4 + kT) * 4;
            aw[o + 0] = CVT_TF32(fc2w[r0 * DD + d0] * LOG2E);
            aw[o + 1] = CVT_TF32(fc2w[r1 * DD + d0] * LOG2E);
            aw[o + 2] = CVT_TF32(fc2w[r0 * DD + d1] * LOG2E);
            aw[o + 3] = CVT_TF32(fc2w[r1 * DD + d1] * LOG2E);
        }

    const int b  = blockIdx.x / (NN / 64);
    const int n0 = (blockIdx.x % (NN / 64)) * 64;
    const int pbase = b * NN + n0 + warp * 8;

    const unsigned feat_a = (unsigned)__cvta_generic_to_shared(&sm->feat[warp][0][0][0]);
    const unsigned fx1_a  = (unsigned)__cvta_generic_to_shared(&sm->fx1[warp][0][0][0]);
    const unsigned conv_a = (unsigned)__cvta_generic_to_shared(&sm->conv[warp][0][0][0]);
    const unsigned agg_a  = (unsigned)__cvta_generic_to_shared(&sm->agg[warp][0][0]);

    {
        int4 iv = *(const int4*)(nidx + (size_t)pbase * KK + lane * 4);
        *(int4*)&sm->idx[warp][lane >> 2][(lane & 3) * 4] = iv;
    }
    __syncthreads();

    const int j2 = lane >> 1, h2 = lane & 1;

    #pragma unroll
    for (int s = 0; s < 4; s++) {
        int idx = sm->idx[warp][s][j2];
        const float* src = g_agg1 + (size_t)(b * NN + idx) * HH + h2 * 8;
        unsigned d = feat_a + s * PTB + j2 * RSB + h2 * 32;
        cp16(d, src); cp16(d + 16, src + 4);
        {
            const float* fs = g_fx1 + (size_t)(pbase + s) * (KK * HH) + j2 * HH + h2 * 8;
            unsigned fd = fx1_a + s * PTB + j2 * RSB + h2 * 32;
            cp16(fd, fs); cp16(fd + 16, fs + 4);
        }
        cp_commit();
    }

    #pragma unroll
    for (int t = 0; t < 4; t++) {
        const int p0 = 2 * t, p1 = p0 + 1;
        const int buf0 = p0 & 3;
        if (t < 3) cp_wait<2>(); else cp_wait<0>();
        __syncwarp();

        // conv2 via tf32 mma for both points
        #pragma unroll
        for (int pt = 0; pt < 2; pt++) {
            const unsigned fbx = fx1_a + (buf0 + pt) * PTB;
            #pragma unroll
            for (int nT = 0; nT < 2; nT++) {
                float c[4] = {bb2c0, bb2c0, bb2c1, bb2c1};
                unsigned xb = fbx + (8 * nT + g) * RSB;
                #pragma unroll
                for (int kT = 0; kT < 2; kT++) {
                    unsigned base = xb + (8 * kT + tq) * 4;
                    uint32_t b0v = LDSU(base);
                    uint32_t b1v = LDSU(base + 16);
                    MMA_TF32(c, &aw2[kT * 4], b0v, b1v);
                }
                int j0 = 8 * nT + 2 * tq, j1 = j0 + 1;
                sm->conv[warp][pt][j0][g] = lrelu(c[0]);
                sm->conv[warp][pt][j1][g] = lrelu(c[1]);
                sm->conv[warp][pt][j0][g + 8] = lrelu(c[2]);
                sm->conv[warp][pt][j1][g + 8] = lrelu(c[3]);
            }
        }
        __syncwarp();

        // fc2 + softmax + pool, both points interleaved
        const unsigned fb0 = feat_a + (buf0 + 0) * PTB, cb0 = conv_a + 0 * PTB;
        const unsigned fb1 = feat_a + (buf0 + 1) * PTB, cb1 = conv_a + 1 * PTB;
        float s0v[16], s1v[16];
        fc_scores(aw, fb0, cb0, g, tq, s0v);
        fc_scores(aw, fb1, cb1, g, tq, s1v);
        #pragma unroll
        for (int i = 0; i < 16; i++) { s0v[i] = EX2(s0v[i]); s1v[i] = EX2(s1v[i]); }
        float4 r0, r1;
        softpool(s0v, fb0, cb0, g, tq, r0);
        softpool(s1v, fb1, cb1, g, tq, r1);
        if (tq == 0) {
            sm->agg[warp][p0][g]      = r0.x; sm->agg[warp][p0][g + 8]  = r0.y;
            sm->agg[warp][p0][g + 16] = r0.z; sm->agg[warp][p0][g + 24] = r0.w;
            sm->agg[warp][p1][g]      = r1.x; sm->agg[warp][p1][g + 8]  = r1.y;
            sm->agg[warp][p1][g + 16] = r1.z; sm->agg[warp][p1][g + 24] = r1.w;
        }

        // prefetch points p0+4, p0+5
        if (t < 2) {
            #pragma unroll
            for (int pt = 0; pt < 2; pt++) {
                int sN = p0 + 4 + pt;
                int idx = sm->idx[warp][sN][j2];
                const float* src = g_agg1 + (size_t)(b * NN + idx) * HH + h2 * 8;
                unsigned d = feat_a + (sN & 3) * PTB + j2 * RSB + h2 * 32;
                cp16(d, src); cp16(d + 16, src + 4);
                {
                    const float* fs = g_fx1 + (size_t)(pbase + sN) * (KK * HH) + j2 * HH + h2 * 8;
                    unsigned fd = fx1_a + (sN & 3) * PTB + j2 * RSB + h2 * 32;
                    cp16(fd, fs); cp16(fd + 16, fs + 4);
                }
                cp_commit();
            }
        }
    }
    __syncwarp();   // agg visible for batched mlp2

    // batched mlp2 (32->32), direct float2 stores to output
    #pragma unroll
    for (int mT = 0; mT < 2; mT++) {
        int r0 = 16 * mT + g, r1 = r0 + 8;
        float s0 = ap2g[r0] * inv_bn, s1 = ap2g[r1] * inv_bn;
        float c[4];
        c[0] = c[1] = ap2b[r0] * s0 + ap2be[r0];
        c[2] = c[3] = ap2b[r1] * s1 + ap2be[r1];
        #pragma unroll
        for (int kT = 0; kT < 4; kT++) {
            int d0 = 8 * kT + tq, d1 = d0 + 4;
            uint32_t af[4];
            af[0] = CVT_TF32(ap2w[r0 * DD + d0] * s0);
            af[1] = CVT_TF32(ap2w[r1 * DD + d0] * s1);
            af[2] = CVT_TF32(ap2w[r0 * DD + d1] * s0);
            af[3] = CVT_TF32(ap2w[r1 * DD + d1] * s1);
            uint32_t b0v = CVT_TF32(LDSF(agg_a + g * 144 + d0 * 4));
            uint32_t b1v = CVT_TF32(LDSF(agg_a + g * 144 + d1 * 4));
            MMA_TF32(c, af, b0v, b1v);
        }
        int nb = n0 + warp * 8 + 2 * tq;
        float2 v0 = make_float2(lrelu(c[0]), lrelu(c[1]));
        float2 v1 = make_float2(lrelu(c[2]), lrelu(c[3]));
        *(float2*)&out[((size_t)b * DD + r0) * NN + nb] = v0;
        *(float2*)&out[((size_t)b * DD + r1) * NN + nb] = v1;
    }
}

// ---------------------------------------------------------------------------
extern "C" void kernel_launch(void* const* d_in, const int* in_sizes, int n_in,
                              void* d_out, int out_size) {
    const float* xyz     = (const float*)d_in[0];
    const float* feature = (const float*)d_in[1];
    const int*   nidx    = (const int*)  d_in[2];
    const float* w1   = (const float*)d_in[3];
    const float* b1   = (const float*)d_in[4];
    const float* g1   = (const float*)d_in[5];
    const float* be1  = (const float*)d_in[6];
    const float* fc1w = (const float*)d_in[7];
    const float* fc1b = (const float*)d_in[8];
    const float* ap1w = (const float*)d_in[9];
    const float* ap1b = (const float*)d_in[10];
    const float* ap1g = (const float*)d_in[11];
    const float* ap1be= (const float*)d_in[12];
    const float* w2   = (const float*)d_in[13];
    const float* b2   = (const float*)d_in[14];
    const float* g2   = (const float*)d_in[15];
    const float* be2  = (const float*)d_in[16];
    const float* fc2w = (const float*)d_in[17];
    const float* fc2b = (const float*)d_in[18];
    const float* ap2w = (const float*)d_in[19];
    const float* ap2b = (const float*)d_in[20];
    const float* ap2g = (const float*)d_in[21];
    const float* ap2be= (const float*)d_in[22];
    float* out = (float*)d_out;

    // idempotent, not a stream op — safe during graph capture, no static guard
    cudaFuncSetAttribute(stage1_kernel,
        cudaFuncAttributeMaxDynamicSharedMemorySize, (int)sizeof(S1Smem));
    cudaFuncSetAttribute(stage2_kernel,
        cudaFuncAttributeMaxDynamicSharedMemorySize, (int)sizeof(S2Smem));

    transpose_feat_kernel<<<dim3(NN / 64, BB), 256>>>(feature);
    stage1_kernel<<<BB * NN / 64, 256, sizeof(S1Smem)>>>(
        xyz, nidx, w1, b1, g1, be1, fc1w, fc1b, ap1w, ap1b, ap1g, ap1be);
    stage2_kernel<<<BB * NN / 64, 256, sizeof(S2Smem)>>>(
        nidx, w2, b2, g2, be2, fc2w, fc2b, ap2w, ap2b, ap2g, ap2be, out);
}

// round 17
// speedup vs baseline: 1.0790x; 1.0790x over previous
#include <cuda_runtime.h>
#include <math.h>
#include <stdint.h>

#define BB 4
#define NN 40960
#define KK 16
#define HH 16
#define DD 32
#define BN_EPS 1e-5f
#define RS 20            // padded row stride (floats) for mma-fed tiles
#define RSB 80           // row stride bytes
#define PTB (KK * RSB)   // bytes per point tile (1280)
#define LOG2E 1.4426950408889634f

__device__ float g_feat_t[BB * NN * HH];
__device__ float g_agg1[BB * NN * HH];
__device__ float g_fx1[(size_t)BB * NN * KK * HH];  // f_xyz1 [b,n,k,16]

__device__ __forceinline__ float lrelu(float y) { return fmaxf(y, 0.2f * y); }

__device__ __forceinline__ uint32_t LDSU(unsigned addr) {
    uint32_t v; asm volatile("ld.shared.b32 %0, [%1];" : "=r"(v) : "r"(addr)); return v;
}
__device__ __forceinline__ float LDSF(unsigned addr) {
    float v; asm volatile("ld.shared.f32 %0, [%1];" : "=f"(v) : "r"(addr)); return v;
}
__device__ __forceinline__ uint32_t CVT_TF32(float x) {
    uint32_t r; asm("cvt.rna.tf32.f32 %0, %1;" : "=r"(r) : "f"(x)); return r;
}
__device__ __forceinline__ float EX2(float x) {
    float r; asm("ex2.approx.f32 %0, %1;" : "=f"(r) : "f"(x)); return r;
}

// tf32 mma m16n8k8: D += A*B
#define MMA_TF32(d, a, b0, b1) \
    asm volatile("mma.sync.aligned.m16n8k8.row.col.f32.tf32.tf32.f32 " \
        "{%0,%1,%2,%3}, {%4,%5,%6,%7}, {%8,%9}, {%0,%1,%2,%3};" \
        : "+f"((d)[0]), "+f"((d)[1]), "+f"((d)[2]), "+f"((d)[3]) \
        : "r"((a)[0]), "r"((a)[1]), "r"((a)[2]), "r"((a)[3]), "r"(b0), "r"(b1))

// ---- cp.async helpers ----
__device__ __forceinline__ void cp16(unsigned dst, const float* src) {
    asm volatile("cp.async.cg.shared.global [%0], [%1], 16;" :: "r"(dst), "l"(src));
}
__device__ __forceinline__ void cp4(unsigned dst, const float* src) {
    asm volatile("cp.async.ca.shared.global [%0], [%1], 4;" :: "r"(dst), "l"(src));
}
__device__ __forceinline__ void cp_commit() {
    asm volatile("cp.async.commit_group;");
}
template <int N> __device__ __forceinline__ void cp_wait() {
    asm volatile("cp.async.wait_group %0;" :: "n"(N));
}

// fc scores: 32 channels x 16 j for one point -> s[16] (lane-distributed)
__device__ __forceinline__ void fc_scores(const uint32_t* aw, unsigned fbuf,
                                          unsigned cbuf, int g, int tq, float* s) {
    #pragma unroll
    for (int nT = 0; nT < 2; nT++) {
        float c0[4] = {0.f, 0.f, 0.f, 0.f}, c1[4] = {0.f, 0.f, 0.f, 0.f};
        int j = g + 8 * nT;
        unsigned xf = fbuf + j * RSB;
        unsigned xc = cbuf + j * RSB;
        #pragma unroll
        for (int kT = 0; kT < 4; kT++) {
            unsigned base = (kT < 2) ? (xf + (8 * kT + tq) * 4)
                                     : (xc + (8 * (kT - 2) + tq) * 4);
            uint32_t b0v = LDSU(base), b1v = LDSU(base + 16);
            MMA_TF32(c0, &aw[(0 * 4 + kT) * 4], b0v, b1v);
            MMA_TF32(c1, &aw[(1 * 4 + kT) * 4], b0v, b1v);
        }
        #pragma unroll
        for (int q = 0; q < 4; q++) {
            s[(nT * 2 + 0) * 4 + q] = c0[q];
            s[(nT * 2 + 1) * 4 + q] = c1[q];
        }
    }
}

// softmax-pool: s holds exp'd scores; result valid on tq==0 lanes
__device__ __forceinline__ void softpool(const float* s, unsigned fbuf, unsigned cbuf,
                                         int g, int tq, float4& r) {
    float p0 = s[0] + s[1] + s[8]  + s[9];
    float p1 = s[2] + s[3] + s[10] + s[11];
    float p2 = s[4] + s[5] + s[12] + s[13];
    float p3 = s[6] + s[7] + s[14] + s[15];
    p0 += __shfl_xor_sync(0xffffffffu, p0, 1); p0 += __shfl_xor_sync(0xffffffffu, p0, 2);
    p1 += __shfl_xor_sync(0xffffffffu, p1, 1); p1 += __shfl_xor_sync(0xffffffffu, p1, 2);
    p2 += __shfl_xor_sync(0xffffffffu, p2, 1); p2 += __shfl_xor_sync(0xffffffffu, p2, 2);
    p3 += __shfl_xor_sync(0xffffffffu, p3, 1); p3 += __shfl_xor_sync(0xffffffffu, p3, 2);
    int j0 = 2 * tq, j1 = j0 + 1, j8 = j0 + 8, j9 = j0 + 9;
    unsigned cF0 = g * 4, cF1 = (g + 8) * 4;
    float a0 = LDSF(fbuf + j0 * RSB + cF0) * s[0] + LDSF(fbuf + j1 * RSB + cF0) * s[1]
             + LDSF(fbuf + j8 * RSB + cF0) * s[8] + LDSF(fbuf + j9 * RSB + cF0) * s[9];
    float a1 = LDSF(fbuf + j0 * RSB + cF1) * s[2] + LDSF(fbuf + j1 * RSB + cF1) * s[3]
             + LDSF(fbuf + j8 * RSB + cF1) * s[10] + LDSF(fbuf + j9 * RSB + cF1) * s[11];
    float a2 = LDSF(cbuf + j0 * RSB + cF0) * s[4] + LDSF(cbuf + j1 * RSB + cF0) * s[5]
             + LDSF(cbuf + j8 * RSB + cF0) * s[12] + LDSF(cbuf + j9 * RSB + cF0) * s[13];
    float a3 = LDSF(cbuf + j0 * RSB + cF1) * s[6] + LDSF(cbuf + j1 * RSB + cF1) * s[7]
             + LDSF(cbuf + j8 * RSB + cF1) * s[14] + LDSF(cbuf + j9 * RSB + cF1) * s[15];
    a0 += __shfl_xor_sync(0xffffffffu, a0, 1); a0 += __shfl_xor_sync(0xffffffffu, a0, 2);
    a1 += __shfl_xor_sync(0xffffffffu, a1, 1); a1 += __shfl_xor_sync(0xffffffffu, a1, 2);
    a2 += __shfl_xor_sync(0xffffffffu, a2, 1); a2 += __shfl_xor_sync(0xffffffffu, a2, 2);
    a3 += __shfl_xor_sync(0xffffffffu, a3, 1); a3 += __shfl_xor_sync(0xffffffffu, a3, 2);
    r.x = __fdividef(a0, p0); r.y = __fdividef(a1, p1);
    r.z = __fdividef(a2, p2); r.w = __fdividef(a3, p3);
}

// ---------------------------------------------------------------------------
__global__ void transpose_feat_kernel(const float* __restrict__ feature) {
    __shared__ float tile[HH][64 + 1];
    int b = blockIdx.y;
    int n0 = blockIdx.x * 64;
    int t = threadIdx.x;
    int i = t & 63, cq = t >> 6;
    #pragma unroll
    for (int cc = cq; cc < HH; cc += 4)
        tile[cc][i] = feature[(b * HH + cc) * NN + n0 + i];
    __syncthreads();
    int c = t & 15, iq = t >> 4;
    #pragma unroll
    for (int ii = iq; ii < 64; ii += 16)
        g_feat_t[(b * NN + n0 + ii) * HH + c] = tile[c][ii];
}

// ---------------------------------------------------------------------------
// Stage 1: 4 warps/CTA, 2 points/iter; conv1 written IN-PLACE into fxyz tiles
// (K-pad cols are dead: their A-fragment weights are zero). Static smem 41KB.
// ---------------------------------------------------------------------------
__global__ void __launch_bounds__(128, 5) stage1_kernel(
    const float* __restrict__ xyz, const int* __restrict__ nidx,
    const float* __restrict__ w1, const float* __restrict__ b1,
    const float* __restrict__ g1, const float* __restrict__ be1,
    const float* __restrict__ fc1w, const float* __restrict__ fc1b,
    const float* __restrict__ ap1w, const float* __restrict__ ap1b,
    const float* __restrict__ ap1g, const float* __restrict__ ap1be)
{
    __shared__ __align__(16) float sh_feat[4][4][KK][RS];   // gather ring
    __shared__ __align__(16) float sh_nxyz[4][4][KK][4];
    __shared__ __align__(16) float sh_fxyz[4][2][KK][RS];   // geometry+conv in-place
    __shared__ __align__(16) float sh_agg[4][8][36];
    __shared__ __align__(16) int   sh_idx[4][8][KK];
    __shared__ float sh_cxyz[4][8][3];

    const int warp = threadIdx.x >> 5;
    const int lane = threadIdx.x & 31;
    const int g = lane >> 2, tq = lane & 3;
    const float inv_bn = rsqrtf(1.0f + BN_EPS);

    // conv1 weight fragments (BN folded, K padded 10->16)
    uint32_t aw1[8]; float bb1c0, bb1c1;
    {
        float s0 = g1[g] * inv_bn, s1 = g1[g + 8] * inv_bn;
        #pragma unroll
        for (int kT = 0; kT < 2; kT++) {
            int d0 = 8 * kT + tq, d1 = d0 + 4;
            float w00 = (d0 < 10) ? w1[g * 10 + d0] * s0 : 0.f;
            float w10 = (d0 < 10) ? w1[(g + 8) * 10 + d0] * s1 : 0.f;
            float w01 = (d1 < 10) ? w1[g * 10 + d1] * s0 : 0.f;
            float w11 = (d1 < 10) ? w1[(g + 8) * 10 + d1] * s1 : 0.f;
            aw1[kT * 4 + 0] = CVT_TF32(w00); aw1[kT * 4 + 1] = CVT_TF32(w10);
            aw1[kT * 4 + 2] = CVT_TF32(w01); aw1[kT * 4 + 3] = CVT_TF32(w11);
        }
        bb1c0 = b1[g] * s0 + be1[g];
        bb1c1 = b1[g + 8] * s1 + be1[g + 8];
    }
    // fc weight fragments (log2e folded)
    uint32_t aw[32];
    #pragma unroll
    for (int mT = 0; mT < 2; mT++)
        #pragma unroll
        for (int kT = 0; kT < 4; kT++) {
            int r0 = 16 * mT + g, r1 = r0 + 8, d0 = 8 * kT + tq, d1 = d0 + 4;
            int o = (mT * 4 + kT) * 4;
            aw[o + 0] = CVT_TF32(fc1w[r0 * DD + d0] * LOG2E);
            aw[o + 1] = CVT_TF32(fc1w[r1 * DD + d0] * LOG2E);
            aw[o + 2] = CVT_TF32(fc1w[r0 * DD + d1] * LOG2E);
            aw[o + 3] = CVT_TF32(fc1w[r1 * DD + d1] * LOG2E);
        }

    const int b  = blockIdx.x / (NN / 32);
    const int n0 = (blockIdx.x % (NN / 32)) * 32;
    const int pbase = b * NN + n0 + warp * 8;

    const unsigned feat_a = (unsigned)__cvta_generic_to_shared(&sh_feat[warp][0][0][0]);
    const unsigned nxyz_a = (unsigned)__cvta_generic_to_shared(&sh_nxyz[warp][0][0][0]);
    const unsigned fxyz_a = (unsigned)__cvta_generic_to_shared(&sh_fxyz[warp][0][0][0]);
    const unsigned agg_a  = (unsigned)__cvta_generic_to_shared(&sh_agg[warp][0][0]);

    {
        int4 iv = *(const int4*)(nidx + (size_t)pbase * KK + lane * 4);
        *(int4*)&sh_idx[warp][lane >> 2][(lane & 3) * 4] = iv;
    }
    if (lane < 24) sh_cxyz[warp][lane / 3][lane % 3] = xyz[pbase * 3 + lane];
    // zero-fill pad cols 10..15 once (finite values; weights there are zero)
    {
        int pt = lane >> 4, j = lane & 15;
        ((float2*)&sh_fxyz[warp][pt][j][10])[0] = make_float2(0.f, 0.f);
        ((float4*)&sh_fxyz[warp][pt][j][12])[0] = make_float4(0.f, 0.f, 0.f, 0.f);
    }
    __syncthreads();

    const int j2 = lane >> 1, h2 = lane & 1;

    #pragma unroll
    for (int s = 0; s < 4; s++) {
        int idx = sh_idx[warp][s][j2];
        const float* src = g_feat_t + (size_t)(b * NN + idx) * HH + h2 * 8;
        unsigned d = feat_a + s * PTB + j2 * RSB + h2 * 32;
        cp16(d, src); cp16(d + 16, src + 4);
        if (lane < KK) {
            int ix = sh_idx[warp][s][lane];
            const float* xs = xyz + (size_t)(b * NN + ix) * 3;
            unsigned dn = nxyz_a + s * 256 + lane * 16;
            cp4(dn, xs); cp4(dn + 4, xs + 1); cp4(dn + 8, xs + 2);
        }
        cp_commit();
    }

    #pragma unroll
    for (int t = 0; t < 4; t++) {
        const int p0 = 2 * t, p1 = p0 + 1;
        const int pn0 = pbase + p0, pn1 = pbase + p1;
        const int buf0 = p0 & 3;
        if (t < 3) cp_wait<2>(); else cp_wait<0>();
        __syncwarp();

        // geometry: all 32 lanes (pt = lane>>4)
        {
            int pt = lane >> 4, j = lane & 15;
            const float* np_ = &sh_nxyz[warp][buf0 + pt][j][0];
            float nx = np_[0], ny = np_[1], nz = np_[2];
            const float* cp_ = &sh_cxyz[warp][p0 + pt][0];
            float cx = cp_[0], cy = cp_[1], cz = cp_[2];
            float rx = cx - nx, ry = cy - ny, rz = cz - nz;
            float dis = sqrtf(rx * rx + ry * ry + rz * rz);
            float4* row = (float4*)&sh_fxyz[warp][pt][j][0];
            row[0] = make_float4(dis, rx, ry, rz);
            row[1] = make_float4(cx, cy, cz, nx);
            ((float2*)&sh_fxyz[warp][pt][j][8])[0] = make_float2(ny, nz);
        }
        __syncwarp();

        // conv1 via tf32 mma for both points, IN-PLACE into fxyz tile
        #pragma unroll
        for (int pt = 0; pt < 2; pt++) {
            size_t gb = (size_t)(pt ? pn1 : pn0) * (KK * HH);
            #pragma unroll
            for (int nT = 0; nT < 2; nT++) {
                float c[4] = {bb1c0, bb1c0, bb1c1, bb1c1};
                unsigned xb = fxyz_a + pt * PTB + (8 * nT + g) * RSB;
                #pragma unroll
                for (int kT = 0; kT < 2; kT++) {
                    unsigned base = xb + (8 * kT + tq) * 4;
                    uint32_t b0v = LDSU(base);
                    uint32_t b1v = LDSU(base + 16);
                    MMA_TF32(c, &aw1[kT * 4], b0v, b1v);
                }
                int j0 = 8 * nT + 2 * tq, j1 = j0 + 1;
                float v0 = lrelu(c[0]), v1 = lrelu(c[1]);
                float v2 = lrelu(c[2]), v3 = lrelu(c[3]);
                sh_fxyz[warp][pt][j0][g] = v0;     sh_fxyz[warp][pt][j1][g] = v1;
                sh_fxyz[warp][pt][j0][g + 8] = v2; sh_fxyz[warp][pt][j1][g + 8] = v3;
                g_fx1[gb + j0 * HH + g] = v0;     g_fx1[gb + j1 * HH + g] = v1;
                g_fx1[gb + j0 * HH + g + 8] = v2; g_fx1[gb + j1 * HH + g + 8] = v3;
            }
        }
        __syncwarp();

        // fc + softmax + pool, both points interleaved (conv data now in fxyz)
        const unsigned fb0 = feat_a + (buf0 + 0) * PTB, cb0 = fxyz_a + 0 * PTB;
        const unsigned fb1 = feat_a + (buf0 + 1) * PTB, cb1 = fxyz_a + 1 * PTB;
        float s0v[16], s1v[16];
        fc_scores(aw, fb0, cb0, g, tq, s0v);
        fc_scores(aw, fb1, cb1, g, tq, s1v);
        #pragma unroll
        for (int i = 0; i < 16; i++) { s0v[i] = EX2(s0v[i]); s1v[i] = EX2(s1v[i]); }
        float4 r0, r1;
        softpool(s0v, fb0, cb0, g, tq, r0);
        softpool(s1v, fb1, cb1, g, tq, r1);
        if (tq == 0) {
            sh_agg[warp][p0][g]      = r0.x; sh_agg[warp][p0][g + 8]  = r0.y;
            sh_agg[warp][p0][g + 16] = r0.z; sh_agg[warp][p0][g + 24] = r0.w;
            sh_agg[warp][p1][g]      = r1.x; sh_agg[warp][p1][g + 8]  = r1.y;
            sh_agg[warp][p1][g + 16] = r1.z; sh_agg[warp][p1][g + 24] = r1.w;
        }

        // prefetch points p0+4, p0+5
        if (t < 2) {
            #pragma unroll
            for (int pt = 0; pt < 2; pt++) {
                int sN = p0 + 4 + pt;
                int idx = sh_idx[warp][sN][j2];
                const float* src = g_feat_t + (size_t)(b * NN + idx) * HH + h2 * 8;
                unsigned d = feat_a + (sN & 3) * PTB + j2 * RSB + h2 * 32;
                cp16(d, src); cp16(d + 16, src + 4);
                if (lane < KK) {
                    int ix = sh_idx[warp][sN][lane];
                    const float* xs = xyz + (size_t)(b * NN + ix) * 3;
                    unsigned dn = nxyz_a + (sN & 3) * 256 + lane * 16;
                    cp4(dn, xs); cp4(dn + 4, xs + 1); cp4(dn + 8, xs + 2);
                }
                cp_commit();
            }
        }
    }
    __syncwarp();   // agg visible for batched mlp

    // batched mlp (32->16) for 8 points via tf32 mma
    {
        float s0 = ap1g[g] * inv_bn, s1 = ap1g[g + 8] * inv_bn;
        float c[4];
        c[0] = c[1] = ap1b[g] * s0 + ap1be[g];
        c[2] = c[3] = ap1b[g + 8] * s1 + ap1be[g + 8];
        #pragma unroll
        for (int kT = 0; kT < 4; kT++) {
            int d0 = 8 * kT + tq, d1 = d0 + 4;
            uint32_t af[4];
            af[0] = CVT_TF32(ap1w[g * DD + d0] * s0);
            af[1] = CVT_TF32(ap1w[(g + 8) * DD + d0] * s1);
            af[2] = CVT_TF32(ap1w[g * DD + d1] * s0);
            af[3] = CVT_TF32(ap1w[(g + 8) * DD + d1] * s1);
            uint32_t b0v = CVT_TF32(LDSF(agg_a + g * 144 + d0 * 4));
            uint32_t b1v = CVT_TF32(LDSF(agg_a + g * 144 + d1 * 4));
            MMA_TF32(c, af, b0v, b1v);
        }
        int p0i = pbase + 2 * tq, p1i = p0i + 1;
        g_agg1[(size_t)p0i * HH + g]     = lrelu(c[0]);
        g_agg1[(size_t)p1i * HH + g]     = lrelu(c[1]);
        g_agg1[(size_t)p0i * HH + g + 8] = lrelu(c[2]);
        g_agg1[(size_t)p1i * HH + g + 8] = lrelu(c[3]);
    }
}

// ---------------------------------------------------------------------------
// Stage 2: 4 warps/CTA, 2 points/iter; conv2 IN-PLACE into fx1 ring buffer.
// Static smem 46.5KB -> 4 CTAs/SM.
// ---------------------------------------------------------------------------
__global__ void __launch_bounds__(128, 4) stage2_kernel(
    const int* __restrict__ nidx,
    const float* __restrict__ w2, const float* __restrict__ b2,
    const float* __restrict__ g2, const float* __restrict__ be2,
    const float* __restrict__ fc2w, const float* __restrict__ fc2b,
    const float* __restrict__ ap2w, const float* __restrict__ ap2b,
    const float* __restrict__ ap2g, const float* __restrict__ ap2be,
    float* __restrict__ out)
{
    __shared__ __align__(16) float sh_feat[4][4][KK][RS];
    __shared__ __align__(16) float sh_fx1[4][4][KK][RS];    // f_xyz1 -> conv2 in-place
    __shared__ __align__(16) float sh_agg[4][8][36];
    __shared__ __align__(16) int   sh_idx[4][8][KK];

    const int warp = threadIdx.x >> 5;
    const int lane = threadIdx.x & 31;
    const int g = lane >> 2, tq = lane & 3;
    const float inv_bn = rsqrtf(1.0f + BN_EPS);

    uint32_t aw2[8]; float bb2c0, bb2c1;
    {
        float s0 = g2[g] * inv_bn, s1 = g2[g + 8] * inv_bn;
        #pragma unroll
        for (int kT = 0; kT < 2; kT++) {
            int d0 = 8 * kT + tq, d1 = d0 + 4;
            aw2[kT * 4 + 0] = CVT_TF32(w2[g * HH + d0] * s0);
            aw2[kT * 4 + 1] = CVT_TF32(w2[(g + 8) * HH + d0] * s1);
            aw2[kT * 4 + 2] = CVT_TF32(w2[g * HH + d1] * s0);
            aw2[kT * 4 + 3] = CVT_TF32(w2[(g + 8) * HH + d1] * s1);
        }
        bb2c0 = b2[g] * s0 + be2[g];
        bb2c1 = b2[g + 8] * s1 + be2[g + 8];
    }
    uint32_t aw[32];
    #pragma unroll
    for (int mT = 0; mT < 2; mT++)
        #pragma unroll
        for (int kT = 0; kT < 4; kT++) {
            int r0 = 16 * mT + g, r1 = r0 + 8, d0 = 8 * kT + tq, d1 = d0 + 4;
            int o = (mT * 4 + kT) * 4;
            aw[o + 0] = CVT_TF32(fc2w[r0 * DD + d0] * LOG2E);
            aw[o + 1] = CVT_TF32(fc2w[r1 * DD + d0] * LOG2E);
            aw[o + 2] = CVT_TF32(fc2w[r0 * DD + d1] * LOG2E);
            aw[o + 3] = CVT_TF32(fc2w[r1 * DD + d1] * LOG2E);
        }

    const int b  = blockIdx.x / (NN / 32);
    const int n0 = (blockIdx.x % (NN / 32)) * 32;
    const int pbase = b * NN + n0 + warp * 8;

    const unsigned feat_a = (unsigned)__cvta_generic_to_shared(&sh_feat[warp][0][0][0]);
    const unsigned fx1_a  = (unsigned)__cvta_generic_to_shared(&sh_fx1[warp][0][0][0]);
    const unsigned agg_a  = (unsigned)__cvta_generic_to_shared(&sh_agg[warp][0][0]);

    {
        int4 iv = *(const int4*)(nidx + (size_t)pbase * KK + lane * 4);
        *(int4*)&sh_idx[warp][lane >> 2][(lane & 3) * 4] = iv;
    }
    __syncthreads();

    const int j2 = lane >> 1, h2 = lane & 1;

    #pragma unroll
    for (int s = 0; s < 4; s++) {
        int idx = sh_idx[warp][s][j2];
        const float* src = g_agg1 + (size_t)(b * NN + idx) * HH + h2 * 8;
        unsigned d = feat_a + s * PTB + j2 * RSB + h2 * 32;
        cp16(d, src); cp16(d + 16, src + 4);
        {
            const float* fs = g_fx1 + (size_t)(pbase + s) * (KK * HH) + j2 * HH + h2 * 8;
            unsigned fd = fx1_a + s * PTB + j2 * RSB + h2 * 32;
            cp16(fd, fs); cp16(fd + 16, fs + 4);
        }
        cp_commit();
    }

    #pragma unroll
    for (int t = 0; t < 4; t++) {
        const int p0 = 2 * t, p1 = p0 + 1;
        const int buf0 = p0 & 3;
        if (t < 3) cp_wait<2>(); else cp_wait<0>();
        __syncwarp();

        // conv2 via tf32 mma for both points, IN-PLACE into fx1 ring buffer
        #pragma unroll
        for (int pt = 0; pt < 2; pt++) {
            const unsigned fbx = fx1_a + (buf0 + pt) * PTB;
            #pragma unroll
            for (int nT = 0; nT < 2; nT++) {
                float c[4] = {bb2c0, bb2c0, bb2c1, bb2c1};
                unsigned xb = fbx + (8 * nT + g) * RSB;
                #pragma unroll
                for (int kT = 0; kT < 2; kT++) {
                    unsigned base = xb + (8 * kT + tq) * 4;
                    uint32_t b0v = LDSU(base);
                    uint32_t b1v = LDSU(base + 16);
                    MMA_TF32(c, &aw2[kT * 4], b0v, b1v);
                }
                int j0 = 8 * nT + 2 * tq, j1 = j0 + 1;
                float* t0 = &sh_fx1[warp][buf0 + pt][j0][0];
                float* t1 = &sh_fx1[warp][buf0 + pt][j1][0];
                t0[g] = lrelu(c[0]);     t1[g] = lrelu(c[1]);
                t0[g + 8] = lrelu(c[2]); t1[g + 8] = lrelu(c[3]);
            }
        }
        __syncwarp();

        // fc2 + softmax + pool, both points interleaved (conv data in fx1 ring)
        const unsigned fb0 = feat_a + (buf0 + 0) * PTB, cb0 = fx1_a + (buf0 + 0) * PTB;
        const unsigned fb1 = feat_a + (buf0 + 1) * PTB, cb1 = fx1_a + (buf0 + 1) * PTB;
        float s0v[16], s1v[16];
        fc_scores(aw, fb0, cb0, g, tq, s0v);
        fc_scores(aw, fb1, cb1, g, tq, s1v);
        #pragma unroll
        for (int i = 0; i < 16; i++) { s0v[i] = EX2(s0v[i]); s1v[i] = EX2(s1v[i]); }
        float4 r0, r1;
        softpool(s0v, fb0, cb0, g, tq, r0);
        softpool(s1v, fb1, cb1, g, tq, r1);
        if (tq == 0) {
            sh_agg[warp][p0][g]      = r0.x; sh_agg[warp][p0][g + 8]  = r0.y;
            sh_agg[warp][p0][g + 16] = r0.z; sh_agg[warp][p0][g + 24] = r0.w;
            sh_agg[warp][p1][g]      = r1.x; sh_agg[warp][p1][g + 8]  = r1.y;
            sh_agg[warp][p1][g + 16] = r1.z; sh_agg[warp][p1][g + 24] = r1.w;
        }

        // prefetch points p0+4, p0+5
        if (t < 2) {
            #pragma unroll
            for (int pt = 0; pt < 2; pt++) {
                int sN = p0 + 4 + pt;
                int idx = sh_idx[warp][sN][j2];
                const float* src = g_agg1 + (size_t)(b * NN + idx) * HH + h2 * 8;
                unsigned d = feat_a + (sN & 3) * PTB + j2 * RSB + h2 * 32;
                cp16(d, src); cp16(d + 16, src + 4);
                {
                    const float* fs = g_fx1 + (size_t)(pbase + sN) * (KK * HH) + j2 * HH + h2 * 8;
                    unsigned fd = fx1_a + (sN & 3) * PTB + j2 * RSB + h2 * 32;
                    cp16(fd, fs); cp16(fd + 16, fs + 4);
                }
                cp_commit();
            }
        }
    }
    __syncwarp();   // agg visible for batched mlp2

    // batched mlp2 (32->32), direct float2 stores to output
    #pragma unroll
    for (int mT = 0; mT < 2; mT++) {
        int r0 = 16 * mT + g, r1 = r0 + 8;
        float s0 = ap2g[r0] * inv_bn, s1 = ap2g[r1] * inv_bn;
        float c[4];
        c[0] = c[1] = ap2b[r0] * s0 + ap2be[r0];
        c[2] = c[3] = ap2b[r1] * s1 + ap2be[r1];
        #pragma unroll
        for (int kT = 0; kT < 4; kT++) {
            int d0 = 8 * kT + tq, d1 = d0 + 4;
            uint32_t af[4];
            af[0] = CVT_TF32(ap2w[r0 * DD + d0] * s0);
            af[1] = CVT_TF32(ap2w[r1 * DD + d0] * s1);
            af[2] = CVT_TF32(ap2w[r0 * DD + d1] * s0);
            af[3] = CVT_TF32(ap2w[r1 * DD + d1] * s1);
            uint32_t b0v = CVT_TF32(LDSF(agg_a + g * 144 + d0 * 4));
            uint32_t b1v = CVT_TF32(LDSF(agg_a + g * 144 + d1 * 4));
            MMA_TF32(c, af, b0v, b1v);
        }
        int nb = n0 + warp * 8 + 2 * tq;
        float2 v0 = make_float2(lrelu(c[0]), lrelu(c[1]));
        float2 v1 = make_float2(lrelu(c[2]), lrelu(c[3]));
        *(float2*)&out[((size_t)b * DD + r0) * NN + nb] = v0;
        *(float2*)&out[((size_t)b * DD + r1) * NN + nb] = v1;
    }
}

// ---------------------------------------------------------------------------
extern "C" void kernel_launch(void* const* d_in, const int* in_sizes, int n_in,
                              void* d_out, int out_size) {
    const float* xyz     = (const float*)d_in[0];
    const float* feature = (const float*)d_in[1];
    const int*   nidx    = (const int*)  d_in[2];
    const float* w1   = (const float*)d_in[3];
    const float* b1   = (const float*)d_in[4];
    const float* g1   = (const float*)d_in[5];
    const float* be1  = (const float*)d_in[6];
    const float* fc1w = (const float*)d_in[7];
    const float* fc1b = (const float*)d_in[8];
    const float* ap1w = (const float*)d_in[9];
    const float* ap1b = (const float*)d_in[10];
    const float* ap1g = (const float*)d_in[11];
    const float* ap1be= (const float*)d_in[12];
    const float* w2   = (const float*)d_in[13];
    const float* b2   = (const float*)d_in[14];
    const float* g2   = (const float*)d_in[15];
    const float* be2  = (const float*)d_in[16];
    const float* fc2w = (const float*)d_in[17];
    const float* fc2b = (const float*)d_in[18];
    const float* ap2w = (const float*)d_in[19];
    const float* ap2b = (const float*)d_in[20];
    const float* ap2g = (const float*)d_in[21];
    const float* ap2be= (const float*)d_in[22];
    float* out = (float*)d_out;

    transpose_feat_kernel<<<dim3(NN / 64, BB), 256>>>(feature);
    stage1_kernel<<<BB * NN / 32, 128>>>(xyz, nidx, w1, b1, g1, be1,
                                         fc1w, fc1b, ap1w, ap1b, ap1g, ap1be);
    stage2_kernel<<<BB * NN / 32, 128>>>(nidx, w2, b2, g2, be2, fc2w, fc2b,
                                         ap2w, ap2b, ap2g, ap2be, out);
}